// round 15
// baseline (speedup 1.0000x reference)
#include <cuda_runtime.h>
#include <cuda_fp16.h>
#include <cstdint>

#define N_ATOMS 500000
#define FDIM 128
#define TM 64
#define TN 128
#define TOTAL_TILES 7817

#define AS_S 68                         // A row stride (uint=half2 words): conflict-free
#define BS_S 20                         // B row stride (uint words): conflict-free
#define AS_WORDS (TM * AS_S)            // 4352
#define BS_WORDS (128 * BS_S)           // 2560 per buffer (32-k chunk)
#define SMEM_BYTES ((AS_WORDS + 2 * BS_WORDS) * 4)   // 37888 < 48KB default

__device__ __constant__ int d_OFFS[12] =
    {0, 10000, 110000, 260000, 410000, 490000, 495000, 497000, 498000, 499000, 499500, 500000};
__device__ __constant__ int d_TCUM[12] =
    {0, 157, 1720, 4064, 6408, 7658, 7737, 7769, 7785, 7801, 7809, 7817};

__device__ int g_idx64;
// W as fp16, pre-transposed: [mat][n][kw], kw = packed (k, k+1) half2
__device__ __align__(16) uint32_t g_wh[21 * 128 * 64];
// Feature table as fp16 (128 MB ~= L2-resident); row = 64 half2 words
__device__ __align__(16) uint32_t g_f16[(size_t)N_ATOMS * (FDIM / 2)];

__device__ __forceinline__ uint32_t pack_h2(float x, float y) {
    __half2 h = __floats2half2_rn(x, y);
    return *reinterpret_cast<uint32_t*>(&h);
}
__device__ __forceinline__ float2 unpack_h2(uint32_t u) {
    return __half22float2(*reinterpret_cast<__half2*>(&u));
}

__device__ __forceinline__ void mma_f16(float* c, const uint32_t* a, const uint32_t* b) {
    asm volatile(
        "mma.sync.aligned.m16n8k16.row.col.f32.f16.f16.f32 "
        "{%0,%1,%2,%3}, {%4,%5,%6,%7}, {%8,%9}, {%0,%1,%2,%3};\n"
        : "+f"(c[0]), "+f"(c[1]), "+f"(c[2]), "+f"(c[3])
        : "r"(a[0]), "r"(a[1]), "r"(a[2]), "r"(a[3]), "r"(b[0]), "r"(b[1]));
}

__device__ __forceinline__ void cp_async16(uint32_t saddr, const void* g) {
    asm volatile("cp.async.cg.shared.global [%0], [%1], 16;" :: "r"(saddr), "l"(g));
}

// -----------------------------------------------------------------------------
// Conversion: feat fp32 -> fp16 table. 16M float4 -> uint2 each.
// -----------------------------------------------------------------------------
__global__ void conv_kernel(const float* __restrict__ feat)
{
    size_t i = (size_t)blockIdx.x * blockDim.x + threadIdx.x;   // 0 .. 16M-1
    if (i < (size_t)N_ATOMS * FDIM / 4) {
        float4 v = __ldg(reinterpret_cast<const float4*>(feat) + i);
        uint2 t;
        t.x = pack_h2(v.x, v.y);
        t.y = pack_h2(v.z, v.w);
        reinterpret_cast<uint2*>(g_f16)[i] = t;
    }
}

// -----------------------------------------------------------------------------
// Prep: probe index width + fp16 W images [mat][n][kw].
// -----------------------------------------------------------------------------
__global__ void prep_kernel(const float* __restrict__ W, const int* __restrict__ a2w)
{
    int i = blockIdx.x * blockDim.x + threadIdx.x;
    if (i < 21 * 128 * 64) {
        int mat = i >> 13;
        int r = i & 8191;
        int n = r >> 6;
        int kw = r & 63;
        const float* Wm = W + mat * (FDIM * TN);
        g_wh[i] = pack_h2(Wm[(2 * kw) * TN + n], Wm[(2 * kw + 1) * TN + n]);
    }
    if (blockIdx.x == 0 && threadIdx.x < 32) {
        int v = a2w[2 * threadIdx.x + 1];
        unsigned m = __ballot_sync(0xffffffffu, v != 0);
        if (threadIdx.x == 0) g_idx64 = (m == 0u) ? 1 : 0;
    }
}

// ---- gather from fp16 table: 4 rows in flight, fp32 accumulation ----
template<int DEG>
__device__ __forceinline__ void gather4(
    const int* __restrict__ adj,
    int rs, int re, int segstart, int rbase, int lane, uint32_t* As)
{
    const uint2* ftab = reinterpret_cast<const uint2*>(g_f16);
    int base[4];
    bool gd[4];
#pragma unroll
    for (int q = 0; q < 4; q++) {
        int r = rs + rbase + q;
        gd[q] = r < re;
        base[q] = (gd[q] ? (r - segstart) : 0) * DEG;
    }
    float4 s[4];
#pragma unroll
    for (int q = 0; q < 4; q++) s[q] = make_float4(0.f, 0.f, 0.f, 0.f);
#pragma unroll
    for (int j = 0; j < DEG; j++) {
        int n[4];
#pragma unroll
        for (int q = 0; q < 4; q++) n[q] = __ldg(adj + base[q] + j);
        uint2 v[4];
#pragma unroll
        for (int q = 0; q < 4; q++)
            v[q] = __ldg(ftab + (long long)n[q] * 32 + lane);
#pragma unroll
        for (int q = 0; q < 4; q++) {
            float2 f0 = unpack_h2(v[q].x);
            float2 f1 = unpack_h2(v[q].y);
            s[q].x += f0.x; s[q].y += f0.y;
            s[q].z += f1.x; s[q].w += f1.y;
        }
    }
#pragma unroll
    for (int q = 0; q < 4; q++) {
        if (!gd[q]) s[q] = make_float4(0.f, 0.f, 0.f, 0.f);
        uint2 t;
        t.x = pack_h2(s[q].x, s[q].y);
        t.y = pack_h2(s[q].z, s[q].w);
        *reinterpret_cast<uint2*>(&As[(rbase + q) * AS_S + lane * 2]) = t;
    }
}

__device__ __noinline__ void gather_generic(
    const long long* __restrict__ adj, int deg,
    int rs, int re, int segstart, int rbase, int lane, uint32_t* As)
{
    const uint2* ftab = reinterpret_cast<const uint2*>(g_f16);
    for (int g = 0; g < 8; g += 4) {
        float4 s[4];
        long long base[4];
        bool gd[4];
#pragma unroll
        for (int q = 0; q < 4; q++) {
            int r = rs + rbase + g + q;
            gd[q] = r < re;
            base[q] = (long long)(gd[q] ? (r - segstart) : 0) * deg;
            s[q] = make_float4(0.f, 0.f, 0.f, 0.f);
        }
        for (int j = 0; j < deg; j++) {
#pragma unroll
            for (int q = 0; q < 4; q++) {
                long long nb = __ldg(adj + base[q] + j);
                uint2 v = __ldg(ftab + nb * 32 + lane);
                float2 f0 = unpack_h2(v.x);
                float2 f1 = unpack_h2(v.y);
                s[q].x += f0.x; s[q].y += f0.y;
                s[q].z += f1.x; s[q].w += f1.y;
            }
        }
#pragma unroll
        for (int q = 0; q < 4; q++) {
            if (!gd[q]) s[q] = make_float4(0.f, 0.f, 0.f, 0.f);
            uint2 t;
            t.x = pack_h2(s[q].x, s[q].y);
            t.y = pack_h2(s[q].z, s[q].w);
            *reinterpret_cast<uint2*>(&As[(rbase + g + q) * AS_S + lane * 2]) = t;
        }
    }
}

// -----------------------------------------------------------------------------
// Fused kernel: 64x128 tile / CTA, 8 warps (32x32 warp tiles), fp16 operands,
// fp32 accum. 4 CTAs/SM. A from fp16 table (gather / direct copy); B cp.async
// double-buffered from fp16 W images. Streaming out stores (__stcs).
// -----------------------------------------------------------------------------
__global__ __launch_bounds__(256, 4)
void fused_graphconv_kernel(
    const float* __restrict__ b,
    float* __restrict__ out,
    const void* __restrict__ a1,  const void* __restrict__ a2,
    const void* __restrict__ a3,  const void* __restrict__ a4,
    const void* __restrict__ a5,  const void* __restrict__ a6,
    const void* __restrict__ a7,  const void* __restrict__ a8,
    const void* __restrict__ a9,  const void* __restrict__ a10)
{
    extern __shared__ uint32_t smem[];
    uint32_t* As = smem;                 // [64][AS_S] half2 words
    uint32_t* Bs = smem + AS_WORDS;      // 2 x [128][BS_S]

    const int bt = blockIdx.x;
    int seg = 0;
#pragma unroll
    for (int s = 1; s <= 10; s++)
        if (bt >= d_TCUM[s]) seg = s;

    const int rs = d_OFFS[seg] + (bt - d_TCUM[seg]) * TM;
    const int re = d_OFFS[seg + 1];
    const int segstart = d_OFFS[seg];

    const void* adj = nullptr;
    switch (seg) {
        case 1:  adj = a1;  break;  case 2:  adj = a2;  break;
        case 3:  adj = a3;  break;  case 4:  adj = a4;  break;
        case 5:  adj = a5;  break;  case 6:  adj = a6;  break;
        case 7:  adj = a7;  break;  case 8:  adj = a8;  break;
        case 9:  adj = a9;  break;  case 10: adj = a10; break;
        default: break;
    }
    const int idx64 = g_idx64;

    const int tid  = threadIdx.x;
    const int warp = tid >> 5;
    const int lane = tid & 31;
    const int wm = (warp >> 2) * 32;
    const int wn = (warp & 3) * 32;
    const int lq = lane >> 2;
    const int lr = lane & 3;

    const int mat_rel  = (seg == 0) ? 20 : 2 * (seg - 1);
    const int mat_self = (seg == 0) ? 20 : 2 * seg - 1;
    const int nChunks = (seg == 0) ? 4 : 8;     // 32-k chunks (4 per pass)

    auto issueB = [&](int c, int buf) {
        const int mat = (seg == 0) ? 20 : ((c < 4) ? mat_rel : mat_self);
        const int ck = c & 3;
        const uint32_t* srcBase = g_wh + mat * 8192 + ck * 16;
        uint32_t* dst = Bs + buf * BS_WORDS;
#pragma unroll
        for (int p = 0; p < 2; p++) {
            int o = tid + p * 256;
            int n = o >> 2;
            int q = o & 3;
            uint32_t sa = (uint32_t)__cvta_generic_to_shared(dst + n * BS_S + q * 4);
            cp_async16(sa, srcBase + n * 64 + q * 4);
        }
        asm volatile("cp.async.commit_group;" ::: "memory");
    };

    auto loadA_self = [&]() {
        const uint2* ftab = reinterpret_cast<const uint2*>(g_f16);
        const int rbase = warp * 8;
#pragma unroll
        for (int g = 0; g < 8; g += 4) {
            uint2 v[4];
#pragma unroll
            for (int q = 0; q < 4; q++) {
                int r = rs + rbase + g + q;
                v[q] = make_uint2(0u, 0u);
                if (r < re)
                    v[q] = __ldg(ftab + (long long)r * 32 + lane);
            }
#pragma unroll
            for (int q = 0; q < 4; q++)
                *reinterpret_cast<uint2*>(&As[(rbase + g + q) * AS_S + lane * 2]) = v[q];
        }
    };

    auto loadA_gather = [&]() {
        const int rbase = warp * 8;
        if (!idx64) {
            const int* a = (const int*)adj;
            switch (seg) {
                case 1:  gather4<1>(a, rs, re, segstart, rbase,   lane, As);
                         gather4<1>(a, rs, re, segstart, rbase+4, lane, As); break;
                case 2:  gather4<2>(a, rs, re, segstart, rbase,   lane, As);
                         gather4<2>(a, rs, re, segstart, rbase+4, lane, As); break;
                case 3:  gather4<3>(a, rs, re, segstart, rbase,   lane, As);
                         gather4<3>(a, rs, re, segstart, rbase+4, lane, As); break;
                case 4:  gather4<4>(a, rs, re, segstart, rbase,   lane, As);
                         gather4<4>(a, rs, re, segstart, rbase+4, lane, As); break;
                case 5:  gather4<5>(a, rs, re, segstart, rbase,   lane, As);
                         gather4<5>(a, rs, re, segstart, rbase+4, lane, As); break;
                case 6:  gather4<6>(a, rs, re, segstart, rbase,   lane, As);
                         gather4<6>(a, rs, re, segstart, rbase+4, lane, As); break;
                case 7:  gather4<7>(a, rs, re, segstart, rbase,   lane, As);
                         gather4<7>(a, rs, re, segstart, rbase+4, lane, As); break;
                case 8:  gather4<8>(a, rs, re, segstart, rbase,   lane, As);
                         gather4<8>(a, rs, re, segstart, rbase+4, lane, As); break;
                case 9:  gather4<9>(a, rs, re, segstart, rbase,   lane, As);
                         gather4<9>(a, rs, re, segstart, rbase+4, lane, As); break;
                default: gather4<10>(a, rs, re, segstart, rbase,   lane, As);
                         gather4<10>(a, rs, re, segstart, rbase+4, lane, As); break;
            }
        } else {
            gather_generic((const long long*)adj, seg, rs, re, segstart, rbase, lane, As);
        }
    };

    // ---- prologue ----
    issueB(0, 0);
    if (seg > 0) loadA_gather(); else loadA_self();

    float acc[2][4][4];
#pragma unroll
    for (int i = 0; i < 2; i++)
#pragma unroll
        for (int j = 0; j < 4; j++)
#pragma unroll
            for (int k = 0; k < 4; k++) acc[i][j][k] = 0.f;

    for (int c = 0; c < nChunks; c++) {
        if (c == 4) {
            __syncthreads();
            loadA_self();
        }
        asm volatile("cp.async.wait_group 0;" ::: "memory");
        __syncthreads();
        if (c + 1 < nChunks) issueB(c + 1, (c + 1) & 1);

        const uint32_t* Bbuf = Bs + (c & 1) * BS_WORDS;
        const int ck = c & 3;
#pragma unroll
        for (int s = 0; s < 2; s++) {
            const int kwA = (ck * 2 + s) * 8 + lr;
            const int kwB = s * 8 + lr;
            uint32_t af[2][4];
#pragma unroll
            for (int mi = 0; mi < 2; mi++) {
                int r0 = wm + 16 * mi + lq;
                af[mi][0] = As[r0 * AS_S + kwA];
                af[mi][1] = As[(r0 + 8) * AS_S + kwA];
                af[mi][2] = As[r0 * AS_S + kwA + 4];
                af[mi][3] = As[(r0 + 8) * AS_S + kwA + 4];
            }
            uint32_t bf[4][2];
#pragma unroll
            for (int nj = 0; nj < 4; nj++) {
                int n0 = wn + 8 * nj + lq;
                bf[nj][0] = Bbuf[n0 * BS_S + kwB];
                bf[nj][1] = Bbuf[n0 * BS_S + kwB + 4];
            }
#pragma unroll
            for (int mi = 0; mi < 2; mi++)
#pragma unroll
                for (int nj = 0; nj < 4; nj++)
                    mma_f16(acc[mi][nj], af[mi], bf[nj]);
        }
    }

    // ---- bias + relu + streaming store ----
    float2 bv[4];
#pragma unroll
    for (int nj = 0; nj < 4; nj++) {
        int n = wn + 8 * nj + 2 * lr;
        float2 bb;
        if (seg == 0) {
            bb.x = __ldg(b + 20 * TN + n);
            bb.y = __ldg(b + 20 * TN + n + 1);
        } else {
            const float* b0 = b + mat_rel * TN;
            const float* b1 = b + mat_self * TN;
            bb.x = __ldg(b0 + n) + __ldg(b1 + n);
            bb.y = __ldg(b0 + n + 1) + __ldg(b1 + n + 1);
        }
        bv[nj] = bb;
    }

#pragma unroll
    for (int mi = 0; mi < 2; mi++) {
        int r0 = rs + wm + 16 * mi + lq;
#pragma unroll
        for (int nj = 0; nj < 4; nj++) {
            int col = wn + 8 * nj + 2 * lr;
            const float* c = acc[mi][nj];
            if (r0 < re) {
                float2 o;
                o.x = fmaxf(c[0] + bv[nj].x, 0.f);
                o.y = fmaxf(c[1] + bv[nj].y, 0.f);
                __stcs(reinterpret_cast<float2*>(out + (long long)r0 * TN + col), o);
            }
            if (r0 + 8 < re) {
                float2 o;
                o.x = fmaxf(c[2] + bv[nj].x, 0.f);
                o.y = fmaxf(c[3] + bv[nj].y, 0.f);
                __stcs(reinterpret_cast<float2*>(out + (long long)(r0 + 8) * TN + col), o);
            }
        }
    }
}

extern "C" void kernel_launch(void* const* d_in, const int* in_sizes, int n_in,
                              void* d_out, int out_size)
{
    const float* feat = nullptr;
    const float* W = nullptr;
    const float* b = nullptr;
    const void* adj[11] = {nullptr};

    for (int i = 0; i < n_in; i++) {
        switch (in_sizes[i]) {
            case 64000000: feat = (const float*)d_in[i]; break;
            case 344064:   W    = (const float*)d_in[i]; break;
            case 2688:     b    = (const float*)d_in[i]; break;
            case 100000:   adj[1]  = d_in[i]; break;
            case 300000:   adj[2]  = d_in[i]; break;
            case 450000:   adj[3]  = d_in[i]; break;
            case 320000:   adj[4]  = d_in[i]; break;
            case 25000:    adj[5]  = d_in[i]; break;
            case 12000:    adj[6]  = d_in[i]; break;
            case 7000:     adj[7]  = d_in[i]; break;
            case 8000:     adj[8]  = d_in[i]; break;
            case 4500:     adj[9]  = d_in[i]; break;
            case 5000:     adj[10] = d_in[i]; break;
            default: break;
        }
    }

    // feat fp32 -> fp16 table (16M float4 units)
    {
        int total = N_ATOMS * FDIM / 4;            // 16,000,000
        conv_kernel<<<(total + 255) / 256, 256>>>(feat);
    }
    prep_kernel<<<(21 * 128 * 64 + 255) / 256, 256>>>(W, (const int*)adj[2]);

    fused_graphconv_kernel<<<TOTAL_TILES, 256, SMEM_BYTES>>>(
        b, (float*)d_out,
        adj[1], adj[2], adj[3], adj[4], adj[5],
        adj[6], adj[7], adj[8], adj[9], adj[10]);
}

// round 16
// speedup vs baseline: 1.1141x; 1.1141x over previous
#include <cuda_runtime.h>
#include <cuda_fp16.h>
#include <cstdint>

#define N_ATOMS 500000
#define FDIM 128
#define TM 128
#define TN 128
#define TOTAL_TILES 3910

#define AS_S 68                         // A row stride (half2 words): conflict-free
#define BS_S 20                         // B row stride (words): conflict-free
#define AS_WORDS (TM * AS_S)            // 8704
#define BS_WORDS (128 * BS_S)           // 2560 per buffer (32-k chunk)
#define SMEM_BYTES ((AS_WORDS + 2 * BS_WORDS) * 4)   // 55296 -> needs attr, 2 CTAs/SM

__device__ __constant__ int d_OFFS[12] =
    {0, 10000, 110000, 260000, 410000, 490000, 495000, 497000, 498000, 499000, 499500, 500000};
__device__ __constant__ int d_TCUM[12] =
    {0, 79, 861, 2033, 3205, 3830, 3870, 3886, 3894, 3902, 3906, 3910};

__device__ int g_idx64;
// W as fp16, pre-transposed: [mat][n][kw], kw = packed (k, k+1) half2
__device__ __align__(16) uint32_t g_wh[21 * 128 * 64];

__device__ __forceinline__ uint32_t pack_h2(float x, float y) {
    __half2 h = __floats2half2_rn(x, y);
    return *reinterpret_cast<uint32_t*>(&h);
}

__device__ __forceinline__ void mma_f16(float* c, const uint32_t* a, const uint32_t* b) {
    asm volatile(
        "mma.sync.aligned.m16n8k16.row.col.f32.f16.f16.f32 "
        "{%0,%1,%2,%3}, {%4,%5,%6,%7}, {%8,%9}, {%0,%1,%2,%3};\n"
        : "+f"(c[0]), "+f"(c[1]), "+f"(c[2]), "+f"(c[3])
        : "r"(a[0]), "r"(a[1]), "r"(a[2]), "r"(a[3]), "r"(b[0]), "r"(b[1]));
}

__device__ __forceinline__ void cp_async16(uint32_t saddr, const void* g) {
    asm volatile("cp.async.cg.shared.global [%0], [%1], 16;" :: "r"(saddr), "l"(g));
}

__global__ void prep_kernel(const float* __restrict__ W, const int* __restrict__ a2w)
{
    int i = blockIdx.x * blockDim.x + threadIdx.x;
    if (i < 21 * 128 * 64) {
        int mat = i >> 13;
        int r = i & 8191;
        int n = r >> 6;
        int kw = r & 63;
        const float* Wm = W + mat * (FDIM * TN);
        g_wh[i] = pack_h2(Wm[(2 * kw) * TN + n], Wm[(2 * kw + 1) * TN + n]);
    }
    if (blockIdx.x == 0 && threadIdx.x < 32) {
        int v = a2w[2 * threadIdx.x + 1];
        unsigned m = __ballot_sync(0xffffffffu, v != 0);
        if (threadIdx.x == 0) g_idx64 = (m == 0u) ? 1 : 0;
    }
}

// ---- 8-rows-in-flight gather (fp32 feat -> fp16 smem) ----
template<int DEG>
__device__ __forceinline__ void gather8(
    const float* __restrict__ feat, const int* __restrict__ adj,
    int rs, int re, int segstart, int rbase, int lane, uint32_t* As)
{
    int base[8];
    bool gd[8];
#pragma unroll
    for (int q = 0; q < 8; q++) {
        int r = rs + rbase + q;
        gd[q] = r < re;
        base[q] = (gd[q] ? (r - segstart) : 0) * DEG;
    }
    float4 s[8];
#pragma unroll
    for (int q = 0; q < 8; q++) s[q] = make_float4(0.f, 0.f, 0.f, 0.f);
#pragma unroll
    for (int j = 0; j < DEG; j++) {
        int n[8];
#pragma unroll
        for (int q = 0; q < 8; q++) n[q] = __ldg(adj + base[q] + j);
#pragma unroll
        for (int q = 0; q < 8; q++) {
            float4 v = __ldg(reinterpret_cast<const float4*>(feat + (long long)n[q] * FDIM) + lane);
            s[q].x += v.x; s[q].y += v.y; s[q].z += v.z; s[q].w += v.w;
        }
    }
#pragma unroll
    for (int q = 0; q < 8; q++) {
        if (!gd[q]) s[q] = make_float4(0.f, 0.f, 0.f, 0.f);
        uint2 t;
        t.x = pack_h2(s[q].x, s[q].y);
        t.y = pack_h2(s[q].z, s[q].w);
        *reinterpret_cast<uint2*>(&As[(rbase + q) * AS_S + lane * 2]) = t;
    }
}

__device__ __noinline__ void gather_generic(
    const float* __restrict__ feat, const long long* __restrict__ adj, int deg,
    int rs, int re, int segstart, int rbase, int lane, uint32_t* As)
{
    for (int g = 0; g < 16; g += 4) {
        float4 s[4];
        long long base[4];
        bool gd[4];
#pragma unroll
        for (int q = 0; q < 4; q++) {
            int r = rs + rbase + g + q;
            gd[q] = r < re;
            base[q] = (long long)(gd[q] ? (r - segstart) : 0) * deg;
            s[q] = make_float4(0.f, 0.f, 0.f, 0.f);
        }
        for (int j = 0; j < deg; j++) {
#pragma unroll
            for (int q = 0; q < 4; q++) {
                long long nb = __ldg(adj + base[q] + j);
                float4 v = __ldg(reinterpret_cast<const float4*>(feat + nb * FDIM) + lane);
                s[q].x += v.x; s[q].y += v.y; s[q].z += v.z; s[q].w += v.w;
            }
        }
#pragma unroll
        for (int q = 0; q < 4; q++) {
            if (!gd[q]) s[q] = make_float4(0.f, 0.f, 0.f, 0.f);
            uint2 t;
            t.x = pack_h2(s[q].x, s[q].y);
            t.y = pack_h2(s[q].z, s[q].w);
            *reinterpret_cast<uint2*>(&As[(rbase + g + q) * AS_S + lane * 2]) = t;
        }
    }
}

// -----------------------------------------------------------------------------
// Fused kernel: 128x128 tile / CTA, 8 warps (warp tile 32Mx64N, (4M,2N) layout),
// fp16 operands, fp32 accum. 2 CTAs/SM. Per pass: [gather/load A (16 rows/warp)]
// -> 4 chunks of 32k, B cp.async double-buffered. __stcs epilogue.
// -----------------------------------------------------------------------------
__global__ __launch_bounds__(256, 2)
void fused_graphconv_kernel(
    const float* __restrict__ feat,
    const float* __restrict__ b,
    float* __restrict__ out,
    const void* __restrict__ a1,  const void* __restrict__ a2,
    const void* __restrict__ a3,  const void* __restrict__ a4,
    const void* __restrict__ a5,  const void* __restrict__ a6,
    const void* __restrict__ a7,  const void* __restrict__ a8,
    const void* __restrict__ a9,  const void* __restrict__ a10)
{
    extern __shared__ uint32_t smem[];
    uint32_t* As = smem;                 // [128][AS_S] half2 words
    uint32_t* Bs = smem + AS_WORDS;      // 2 x [128][BS_S]

    const int bt = blockIdx.x;
    int seg = 0;
#pragma unroll
    for (int s = 1; s <= 10; s++)
        if (bt >= d_TCUM[s]) seg = s;

    const int rs = d_OFFS[seg] + (bt - d_TCUM[seg]) * TM;
    const int re = d_OFFS[seg + 1];
    const int segstart = d_OFFS[seg];

    const void* adj = nullptr;
    switch (seg) {
        case 1:  adj = a1;  break;  case 2:  adj = a2;  break;
        case 3:  adj = a3;  break;  case 4:  adj = a4;  break;
        case 5:  adj = a5;  break;  case 6:  adj = a6;  break;
        case 7:  adj = a7;  break;  case 8:  adj = a8;  break;
        case 9:  adj = a9;  break;  case 10: adj = a10; break;
        default: break;
    }
    const int idx64 = g_idx64;

    const int tid  = threadIdx.x;
    const int warp = tid >> 5;
    const int lane = tid & 31;
    const int wm = (warp >> 1) * 32;     // 4 M groups
    const int wn = (warp & 1) * 64;      // 2 N groups
    const int lq = lane >> 2;
    const int lr = lane & 3;

    const int mat_rel  = (seg == 0) ? 20 : 2 * (seg - 1);
    const int mat_self = (seg == 0) ? 20 : 2 * seg - 1;
    const int nChunks = (seg == 0) ? 4 : 8;     // 32-k chunks (4 per pass)

    auto issueB = [&](int c, int buf) {
        const int mat = (seg == 0) ? 20 : ((c < 4) ? mat_rel : mat_self);
        const int ck = c & 3;
        const uint32_t* srcBase = g_wh + mat * 8192 + ck * 16;
        uint32_t* dst = Bs + buf * BS_WORDS;
#pragma unroll
        for (int p = 0; p < 2; p++) {
            int o = tid + p * 256;
            int n = o >> 2;
            int q = o & 3;
            uint32_t sa = (uint32_t)__cvta_generic_to_shared(dst + n * BS_S + q * 4);
            cp_async16(sa, srcBase + n * 64 + q * 4);
        }
        asm volatile("cp.async.commit_group;" ::: "memory");
    };

    auto loadA_self = [&]() {
        const int rbase = warp * 16;
#pragma unroll
        for (int g = 0; g < 16; g += 4) {
            float4 v[4];
#pragma unroll
            for (int q = 0; q < 4; q++) {
                int r = rs + rbase + g + q;
                v[q] = make_float4(0.f, 0.f, 0.f, 0.f);
                if (r < re)
                    v[q] = __ldg(reinterpret_cast<const float4*>(feat + (long long)r * FDIM) + lane);
            }
#pragma unroll
            for (int q = 0; q < 4; q++) {
                uint2 t;
                t.x = pack_h2(v[q].x, v[q].y);
                t.y = pack_h2(v[q].z, v[q].w);
                *reinterpret_cast<uint2*>(&As[(rbase + g + q) * AS_S + lane * 2]) = t;
            }
        }
    };

    auto loadA_gather = [&]() {
        const int rbase = warp * 16;
        if (!idx64) {
            const int* a = (const int*)adj;
            switch (seg) {
                case 1:  gather8<1>(feat, a, rs, re, segstart, rbase,   lane, As);
                         gather8<1>(feat, a, rs, re, segstart, rbase+8, lane, As); break;
                case 2:  gather8<2>(feat, a, rs, re, segstart, rbase,   lane, As);
                         gather8<2>(feat, a, rs, re, segstart, rbase+8, lane, As); break;
                case 3:  gather8<3>(feat, a, rs, re, segstart, rbase,   lane, As);
                         gather8<3>(feat, a, rs, re, segstart, rbase+8, lane, As); break;
                case 4:  gather8<4>(feat, a, rs, re, segstart, rbase,   lane, As);
                         gather8<4>(feat, a, rs, re, segstart, rbase+8, lane, As); break;
                case 5:  gather8<5>(feat, a, rs, re, segstart, rbase,   lane, As);
                         gather8<5>(feat, a, rs, re, segstart, rbase+8, lane, As); break;
                case 6:  gather8<6>(feat, a, rs, re, segstart, rbase,   lane, As);
                         gather8<6>(feat, a, rs, re, segstart, rbase+8, lane, As); break;
                case 7:  gather8<7>(feat, a, rs, re, segstart, rbase,   lane, As);
                         gather8<7>(feat, a, rs, re, segstart, rbase+8, lane, As); break;
                case 8:  gather8<8>(feat, a, rs, re, segstart, rbase,   lane, As);
                         gather8<8>(feat, a, rs, re, segstart, rbase+8, lane, As); break;
                case 9:  gather8<9>(feat, a, rs, re, segstart, rbase,   lane, As);
                         gather8<9>(feat, a, rs, re, segstart, rbase+8, lane, As); break;
                default: gather8<10>(feat, a, rs, re, segstart, rbase,   lane, As);
                         gather8<10>(feat, a, rs, re, segstart, rbase+8, lane, As); break;
            }
        } else {
            gather_generic(feat, (const long long*)adj, seg, rs, re, segstart, rbase, lane, As);
        }
    };

    // ---- prologue: B(0) in flight during the first A phase ----
    issueB(0, 0);
    if (seg > 0) loadA_gather(); else loadA_self();

    float acc[2][8][4];
#pragma unroll
    for (int i = 0; i < 2; i++)
#pragma unroll
        for (int j = 0; j < 8; j++)
#pragma unroll
            for (int k = 0; k < 4; k++) acc[i][j][k] = 0.f;

    for (int c = 0; c < nChunks; c++) {
        if (c == 4) {
            __syncthreads();             // all warps done reading As (pass 0)
            loadA_self();                // overlaps in-flight B(4)
        }
        asm volatile("cp.async.wait_group 0;" ::: "memory");
        __syncthreads();
        if (c + 1 < nChunks) issueB(c + 1, (c + 1) & 1);

        const uint32_t* Bbuf = Bs + (c & 1) * BS_WORDS;
        const int ck = c & 3;
#pragma unroll
        for (int s = 0; s < 2; s++) {    // two k16 steps per 32-k chunk
            const int kwA = (ck * 2 + s) * 8 + lr;
            const int kwB = s * 8 + lr;
            uint32_t af[2][4];
#pragma unroll
            for (int mi = 0; mi < 2; mi++) {
                int r0 = wm + 16 * mi + lq;
                af[mi][0] = As[r0 * AS_S + kwA];
                af[mi][1] = As[(r0 + 8) * AS_S + kwA];
                af[mi][2] = As[r0 * AS_S + kwA + 4];
                af[mi][3] = As[(r0 + 8) * AS_S + kwA + 4];
            }
            uint32_t bf[8][2];
#pragma unroll
            for (int nj = 0; nj < 8; nj++) {
                int n0 = wn + 8 * nj + lq;
                bf[nj][0] = Bbuf[n0 * BS_S + kwB];
                bf[nj][1] = Bbuf[n0 * BS_S + kwB + 4];
            }
#pragma unroll
            for (int mi = 0; mi < 2; mi++)
#pragma unroll
                for (int nj = 0; nj < 8; nj++)
                    mma_f16(acc[mi][nj], af[mi], bf[nj]);
        }
    }

    // ---- bias + relu + streaming store ----
    float2 bv[8];
#pragma unroll
    for (int nj = 0; nj < 8; nj++) {
        int n = wn + 8 * nj + 2 * lr;
        float2 bb;
        if (seg == 0) {
            bb.x = __ldg(b + 20 * TN + n);
            bb.y = __ldg(b + 20 * TN + n + 1);
        } else {
            const float* b0 = b + mat_rel * TN;
            const float* b1 = b + mat_self * TN;
            bb.x = __ldg(b0 + n) + __ldg(b1 + n);
            bb.y = __ldg(b0 + n + 1) + __ldg(b1 + n + 1);
        }
        bv[nj] = bb;
    }

#pragma unroll
    for (int mi = 0; mi < 2; mi++) {
        int r0 = rs + wm + 16 * mi + lq;
#pragma unroll
        for (int nj = 0; nj < 8; nj++) {
            int col = wn + 8 * nj + 2 * lr;
            const float* c = acc[mi][nj];
            if (r0 < re) {
                float2 o;
                o.x = fmaxf(c[0] + bv[nj].x, 0.f);
                o.y = fmaxf(c[1] + bv[nj].y, 0.f);
                __stcs(reinterpret_cast<float2*>(out + (long long)r0 * TN + col), o);
            }
            if (r0 + 8 < re) {
                float2 o;
                o.x = fmaxf(c[2] + bv[nj].x, 0.f);
                o.y = fmaxf(c[3] + bv[nj].y, 0.f);
                __stcs(reinterpret_cast<float2*>(out + (long long)(r0 + 8) * TN + col), o);
            }
        }
    }
}

extern "C" void kernel_launch(void* const* d_in, const int* in_sizes, int n_in,
                              void* d_out, int out_size)
{
    const float* feat = nullptr;
    const float* W = nullptr;
    const float* b = nullptr;
    const void* adj[11] = {nullptr};

    for (int i = 0; i < n_in; i++) {
        switch (in_sizes[i]) {
            case 64000000: feat = (const float*)d_in[i]; break;
            case 344064:   W    = (const float*)d_in[i]; break;
            case 2688:     b    = (const float*)d_in[i]; break;
            case 100000:   adj[1]  = d_in[i]; break;
            case 300000:   adj[2]  = d_in[i]; break;
            case 450000:   adj[3]  = d_in[i]; break;
            case 320000:   adj[4]  = d_in[i]; break;
            case 25000:    adj[5]  = d_in[i]; break;
            case 12000:    adj[6]  = d_in[i]; break;
            case 7000:     adj[7]  = d_in[i]; break;
            case 8000:     adj[8]  = d_in[i]; break;
            case 4500:     adj[9]  = d_in[i]; break;
            case 5000:     adj[10] = d_in[i]; break;
            default: break;
        }
    }

    // 55296 B dynamic smem > 48 KB default -> attribute required (static-guarded:
    // set during the correctness run; capture call contains only launches).
    static bool attr_set = false;
    if (!attr_set) {
        cudaFuncSetAttribute(fused_graphconv_kernel,
                             cudaFuncAttributeMaxDynamicSharedMemorySize, SMEM_BYTES);
        attr_set = true;
    }

    prep_kernel<<<(21 * 128 * 64 + 255) / 256, 256>>>(W, (const int*)adj[2]);

    fused_graphconv_kernel<<<TOTAL_TILES, 256, SMEM_BYTES>>>(
        feat, b, (float*)d_out,
        adj[1], adj[2], adj[3], adj[4], adj[5],
        adj[6], adj[7], adj[8], adj[9], adj[10]);
}

// round 17
// speedup vs baseline: 1.1313x; 1.0155x over previous
#include <cuda_runtime.h>
#include <cuda_fp16.h>
#include <cstdint>

#define N_ATOMS 500000
#define FDIM 128
#define TM 64
#define TN 128
#define TOTAL_TILES 7817

#define AS_S 68                         // A row stride (half2 words): conflict-free
#define BS_S 20                         // B row stride (words): conflict-free
#define AS_WORDS (TM * AS_S)            // 4352
#define BS_WORDS (128 * BS_S)           // 2560 per buffer (32-k chunk)
#define SMEM_BYTES ((AS_WORDS + 2 * BS_WORDS) * 4)   // 37888 < 48KB default

__device__ __constant__ int d_OFFS[12] =
    {0, 10000, 110000, 260000, 410000, 490000, 495000, 497000, 498000, 499000, 499500, 500000};
__device__ __constant__ int d_TCUM[12] =
    {0, 157, 1720, 4064, 6408, 7658, 7737, 7769, 7785, 7801, 7809, 7817};

__device__ int g_idx64;
// W as fp16, pre-transposed: [mat][n][kw], kw = packed (k, k+1) half2
__device__ __align__(16) uint32_t g_wh[21 * 128 * 64];

__device__ __forceinline__ uint32_t pack_h2(float x, float y) {
    __half2 h = __floats2half2_rn(x, y);
    return *reinterpret_cast<uint32_t*>(&h);
}

__device__ __forceinline__ void mma_f16(float* c, const uint32_t* a, const uint32_t* b) {
    asm volatile(
        "mma.sync.aligned.m16n8k16.row.col.f32.f16.f16.f32 "
        "{%0,%1,%2,%3}, {%4,%5,%6,%7}, {%8,%9}, {%0,%1,%2,%3};\n"
        : "+f"(c[0]), "+f"(c[1]), "+f"(c[2]), "+f"(c[3])
        : "r"(a[0]), "r"(a[1]), "r"(a[2]), "r"(a[3]), "r"(b[0]), "r"(b[1]));
}

__device__ __forceinline__ void cp_async16(uint32_t saddr, const void* g) {
    asm volatile("cp.async.cg.shared.global [%0], [%1], 16;" :: "r"(saddr), "l"(g));
}

__global__ void prep_kernel(const float* __restrict__ W, const int* __restrict__ a2w)
{
    int i = blockIdx.x * blockDim.x + threadIdx.x;
    if (i < 21 * 128 * 64) {
        int mat = i >> 13;
        int r = i & 8191;
        int n = r >> 6;
        int kw = r & 63;
        const float* Wm = W + mat * (FDIM * TN);
        g_wh[i] = pack_h2(Wm[(2 * kw) * TN + n], Wm[(2 * kw + 1) * TN + n]);
    }
    if (blockIdx.x == 0 && threadIdx.x < 32) {
        int v = a2w[2 * threadIdx.x + 1];
        unsigned m = __ballot_sync(0xffffffffu, v != 0);
        if (threadIdx.x == 0) g_idx64 = (m == 0u) ? 1 : 0;
    }
}

// ---- 8-rows-in-flight gather (fp32 feat -> fp16 smem) ----
template<int DEG>
__device__ __forceinline__ void gather8(
    const float* __restrict__ feat, const int* __restrict__ adj,
    int rs, int re, int segstart, int rbase, int lane, uint32_t* As)
{
    int base[8];
    bool gd[8];
#pragma unroll
    for (int q = 0; q < 8; q++) {
        int r = rs + rbase + q;
        gd[q] = r < re;
        base[q] = (gd[q] ? (r - segstart) : 0) * DEG;
    }
    float4 s[8];
#pragma unroll
    for (int q = 0; q < 8; q++) s[q] = make_float4(0.f, 0.f, 0.f, 0.f);
#pragma unroll
    for (int j = 0; j < DEG; j++) {
        int n[8];
#pragma unroll
        for (int q = 0; q < 8; q++) n[q] = __ldg(adj + base[q] + j);
#pragma unroll
        for (int q = 0; q < 8; q++) {
            float4 v = __ldg(reinterpret_cast<const float4*>(feat + (long long)n[q] * FDIM) + lane);
            s[q].x += v.x; s[q].y += v.y; s[q].z += v.z; s[q].w += v.w;
        }
    }
#pragma unroll
    for (int q = 0; q < 8; q++) {
        if (!gd[q]) s[q] = make_float4(0.f, 0.f, 0.f, 0.f);
        uint2 t;
        t.x = pack_h2(s[q].x, s[q].y);
        t.y = pack_h2(s[q].z, s[q].w);
        *reinterpret_cast<uint2*>(&As[(rbase + q) * AS_S + lane * 2]) = t;
    }
}

__device__ __noinline__ void gather_generic(
    const float* __restrict__ feat, const long long* __restrict__ adj, int deg,
    int rs, int re, int segstart, int rbase, int lane, uint32_t* As)
{
    for (int g = 0; g < 8; g += 4) {
        float4 s[4];
        long long base[4];
        bool gd[4];
#pragma unroll
        for (int q = 0; q < 4; q++) {
            int r = rs + rbase + g + q;
            gd[q] = r < re;
            base[q] = (long long)(gd[q] ? (r - segstart) : 0) * deg;
            s[q] = make_float4(0.f, 0.f, 0.f, 0.f);
        }
        for (int j = 0; j < deg; j++) {
#pragma unroll
            for (int q = 0; q < 4; q++) {
                long long nb = __ldg(adj + base[q] + j);
                float4 v = __ldg(reinterpret_cast<const float4*>(feat + nb * FDIM) + lane);
                s[q].x += v.x; s[q].y += v.y; s[q].z += v.z; s[q].w += v.w;
            }
        }
#pragma unroll
        for (int q = 0; q < 4; q++) {
            if (!gd[q]) s[q] = make_float4(0.f, 0.f, 0.f, 0.f);
            uint2 t;
            t.x = pack_h2(s[q].x, s[q].y);
            t.y = pack_h2(s[q].z, s[q].w);
            *reinterpret_cast<uint2*>(&As[(rbase + g + q) * AS_S + lane * 2]) = t;
        }
    }
}

// -----------------------------------------------------------------------------
// Fused kernel: 64x128 tile / CTA, 8 warps (warp tile 32x32), fp16 operands,
// fp32 accum. 3 CTAs/SM (reg cap 85 -> gather8 fits, acc 32). Per pass:
// [gather8/load A] -> 4 chunks of 32k, B cp.async double-buffered. __stcs out.
// -----------------------------------------------------------------------------
__global__ __launch_bounds__(256, 3)
void fused_graphconv_kernel(
    const float* __restrict__ feat,
    const float* __restrict__ b,
    float* __restrict__ out,
    const void* __restrict__ a1,  const void* __restrict__ a2,
    const void* __restrict__ a3,  const void* __restrict__ a4,
    const void* __restrict__ a5,  const void* __restrict__ a6,
    const void* __restrict__ a7,  const void* __restrict__ a8,
    const void* __restrict__ a9,  const void* __restrict__ a10)
{
    extern __shared__ uint32_t smem[];
    uint32_t* As = smem;                 // [64][AS_S] half2 words
    uint32_t* Bs = smem + AS_WORDS;      // 2 x [128][BS_S]

    const int bt = blockIdx.x;
    int seg = 0;
#pragma unroll
    for (int s = 1; s <= 10; s++)
        if (bt >= d_TCUM[s]) seg = s;

    const int rs = d_OFFS[seg] + (bt - d_TCUM[seg]) * TM;
    const int re = d_OFFS[seg + 1];
    const int segstart = d_OFFS[seg];

    const void* adj = nullptr;
    switch (seg) {
        case 1:  adj = a1;  break;  case 2:  adj = a2;  break;
        case 3:  adj = a3;  break;  case 4:  adj = a4;  break;
        case 5:  adj = a5;  break;  case 6:  adj = a6;  break;
        case 7:  adj = a7;  break;  case 8:  adj = a8;  break;
        case 9:  adj = a9;  break;  case 10: adj = a10; break;
        default: break;
    }
    const int idx64 = g_idx64;

    const int tid  = threadIdx.x;
    const int warp = tid >> 5;
    const int lane = tid & 31;
    const int wm = (warp >> 2) * 32;     // 2 M groups
    const int wn = (warp & 3) * 32;      // 4 N groups
    const int lq = lane >> 2;
    const int lr = lane & 3;

    const int mat_rel  = (seg == 0) ? 20 : 2 * (seg - 1);
    const int mat_self = (seg == 0) ? 20 : 2 * seg - 1;
    const int nChunks = (seg == 0) ? 4 : 8;     // 32-k chunks (4 per pass)

    auto issueB = [&](int c, int buf) {
        const int mat = (seg == 0) ? 20 : ((c < 4) ? mat_rel : mat_self);
        const int ck = c & 3;
        const uint32_t* srcBase = g_wh + mat * 8192 + ck * 16;
        uint32_t* dst = Bs + buf * BS_WORDS;
#pragma unroll
        for (int p = 0; p < 2; p++) {
            int o = tid + p * 256;
            int n = o >> 2;
            int q = o & 3;
            uint32_t sa = (uint32_t)__cvta_generic_to_shared(dst + n * BS_S + q * 4);
            cp_async16(sa, srcBase + n * 64 + q * 4);
        }
        asm volatile("cp.async.commit_group;" ::: "memory");
    };

    auto loadA_self = [&]() {
        const int rbase = warp * 8;
        float4 v[8];
#pragma unroll
        for (int q = 0; q < 8; q++) {
            int r = rs + rbase + q;
            v[q] = make_float4(0.f, 0.f, 0.f, 0.f);
            if (r < re)
                v[q] = __ldg(reinterpret_cast<const float4*>(feat + (long long)r * FDIM) + lane);
        }
#pragma unroll
        for (int q = 0; q < 8; q++) {
            uint2 t;
            t.x = pack_h2(v[q].x, v[q].y);
            t.y = pack_h2(v[q].z, v[q].w);
            *reinterpret_cast<uint2*>(&As[(rbase + q) * AS_S + lane * 2]) = t;
        }
    };

    auto loadA_gather = [&]() {
        const int rbase = warp * 8;
        if (!idx64) {
            const int* a = (const int*)adj;
            switch (seg) {
                case 1:  gather8<1>(feat, a, rs, re, segstart, rbase, lane, As); break;
                case 2:  gather8<2>(feat, a, rs, re, segstart, rbase, lane, As); break;
                case 3:  gather8<3>(feat, a, rs, re, segstart, rbase, lane, As); break;
                case 4:  gather8<4>(feat, a, rs, re, segstart, rbase, lane, As); break;
                case 5:  gather8<5>(feat, a, rs, re, segstart, rbase, lane, As); break;
                case 6:  gather8<6>(feat, a, rs, re, segstart, rbase, lane, As); break;
                case 7:  gather8<7>(feat, a, rs, re, segstart, rbase, lane, As); break;
                case 8:  gather8<8>(feat, a, rs, re, segstart, rbase, lane, As); break;
                case 9:  gather8<9>(feat, a, rs, re, segstart, rbase, lane, As); break;
                default: gather8<10>(feat, a, rs, re, segstart, rbase, lane, As); break;
            }
        } else {
            gather_generic(feat, (const long long*)adj, seg, rs, re, segstart, rbase, lane, As);
        }
    };

    // ---- prologue: B(0) in flight during the first A phase ----
    issueB(0, 0);
    if (seg > 0) loadA_gather(); else loadA_self();

    float acc[2][4][4];
#pragma unroll
    for (int i = 0; i < 2; i++)
#pragma unroll
        for (int j = 0; j < 4; j++)
#pragma unroll
            for (int k = 0; k < 4; k++) acc[i][j][k] = 0.f;

    for (int c = 0; c < nChunks; c++) {
        if (c == 4) {
            __syncthreads();             // all warps done reading As (pass 0)
            loadA_self();                // overlaps in-flight B(4)
        }
        asm volatile("cp.async.wait_group 0;" ::: "memory");
        __syncthreads();
        if (c + 1 < nChunks) issueB(c + 1, (c + 1) & 1);

        const uint32_t* Bbuf = Bs + (c & 1) * BS_WORDS;
        const int ck = c & 3;
#pragma unroll
        for (int s = 0; s < 2; s++) {    // two k16 steps per 32-k chunk
            const int kwA = (ck * 2 + s) * 8 + lr;
            const int kwB = s * 8 + lr;
            uint32_t af[2][4];
#pragma unroll
            for (int mi = 0; mi < 2; mi++) {
                int r0 = wm + 16 * mi + lq;
                af[mi][0] = As[r0 * AS_S + kwA];
                af[mi][1] = As[(r0 + 8) * AS_S + kwA];
                af[mi][2] = As[r0 * AS_S + kwA + 4];
                af[mi][3] = As[(r0 + 8) * AS_S + kwA + 4];
            }
            uint32_t bf[4][2];
#pragma unroll
            for (int nj = 0; nj < 4; nj++) {
                int n0 = wn + 8 * nj + lq;
                bf[nj][0] = Bbuf[n0 * BS_S + kwB];
                bf[nj][1] = Bbuf[n0 * BS_S + kwB + 4];
            }
#pragma unroll
            for (int mi = 0; mi < 2; mi++)
#pragma unroll
                for (int nj = 0; nj < 4; nj++)
                    mma_f16(acc[mi][nj], af[mi], bf[nj]);
        }
    }

    // ---- bias + relu + streaming store ----
    float2 bv[4];
#pragma unroll
    for (int nj = 0; nj < 4; nj++) {
        int n = wn + 8 * nj + 2 * lr;
        float2 bb;
        if (seg == 0) {
            bb.x = __ldg(b + 20 * TN + n);
            bb.y = __ldg(b + 20 * TN + n + 1);
        } else {
            const float* b0 = b + mat_rel * TN;
            const float* b1 = b + mat_self * TN;
            bb.x = __ldg(b0 + n) + __ldg(b1 + n);
            bb.y = __ldg(b0 + n + 1) + __ldg(b1 + n + 1);
        }
        bv[nj] = bb;
    }

#pragma unroll
    for (int mi = 0; mi < 2; mi++) {
        int r0 = rs + wm + 16 * mi + lq;
#pragma unroll
        for (int nj = 0; nj < 4; nj++) {
            int col = wn + 8 * nj + 2 * lr;
            const float* c = acc[mi][nj];
            if (r0 < re) {
                float2 o;
                o.x = fmaxf(c[0] + bv[nj].x, 0.f);
                o.y = fmaxf(c[1] + bv[nj].y, 0.f);
                __stcs(reinterpret_cast<float2*>(out + (long long)r0 * TN + col), o);
            }
            if (r0 + 8 < re) {
                float2 o;
                o.x = fmaxf(c[2] + bv[nj].x, 0.f);
                o.y = fmaxf(c[3] + bv[nj].y, 0.f);
                __stcs(reinterpret_cast<float2*>(out + (long long)(r0 + 8) * TN + col), o);
            }
        }
    }
}

extern "C" void kernel_launch(void* const* d_in, const int* in_sizes, int n_in,
                              void* d_out, int out_size)
{
    const float* feat = nullptr;
    const float* W = nullptr;
    const float* b = nullptr;
    const void* adj[11] = {nullptr};

    for (int i = 0; i < n_in; i++) {
        switch (in_sizes[i]) {
            case 64000000: feat = (const float*)d_in[i]; break;
            case 344064:   W    = (const float*)d_in[i]; break;
            case 2688:     b    = (const float*)d_in[i]; break;
            case 100000:   adj[1]  = d_in[i]; break;
            case 300000:   adj[2]  = d_in[i]; break;
            case 450000:   adj[3]  = d_in[i]; break;
            case 320000:   adj[4]  = d_in[i]; break;
            case 25000:    adj[5]  = d_in[i]; break;
            case 12000:    adj[6]  = d_in[i]; break;
            case 7000:     adj[7]  = d_in[i]; break;
            case 8000:     adj[8]  = d_in[i]; break;
            case 4500:     adj[9]  = d_in[i]; break;
            case 5000:     adj[10] = d_in[i]; break;
            default: break;
        }
    }

    prep_kernel<<<(21 * 128 * 64 + 255) / 256, 256>>>(W, (const int*)adj[2]);

    fused_graphconv_kernel<<<TOTAL_TILES, 256, SMEM_BYTES>>>(
        feat, b, (float*)d_out,
        adj[1], adj[2], adj[3], adj[4], adj[5],
        adj[6], adj[7], adj[8], adj[9], adj[10]);
}